// round 3
// baseline (speedup 1.0000x reference)
#include <cuda_runtime.h>
#include <cuda_bf16.h>

#define N_NODES 100000
#define N_EDGES 3200000
#define IN_FEAT 512
#define HID 32

// ---------------- device scratch (static, no allocation) ----------------
__device__ float g_deg[N_NODES];
__device__ float g_dinv[N_NODES];
__device__ float g_h[(size_t)N_NODES * HID];    // linear-transform output
__device__ float g_agg[(size_t)N_NODES * HID];  // aggregation accumulator

// ---------------- degree / norm ----------------
__global__ void zero_deg_kernel() {
    int i = blockIdx.x * blockDim.x + threadIdx.x;
    if (i < N_NODES) g_deg[i] = 0.0f;
}

__global__ void deg_kernel(const int* __restrict__ dst) {
    int e = blockIdx.x * blockDim.x + threadIdx.x;
    if (e < N_EDGES) atomicAdd(&g_deg[dst[e]], 1.0f);
}

__global__ void dinv_kernel() {
    int i = blockIdx.x * blockDim.x + threadIdx.x;
    if (i < N_NODES) g_dinv[i] = rsqrtf(g_deg[i] + 1.0f);
}

// ---------------- GEMM1: [N,512] @ [512,32] ----------------
// block = 256 threads; each block computes a 32-row x 32-col output tile.
// Thread (rgrp, col) computes 4 rows at one col. K tiled by 64.
#define TK 64
__global__ __launch_bounds__(256) void gemm1_kernel(
    const float* __restrict__ x, const float* __restrict__ W,
    float* __restrict__ out)
{
    __shared__ float Xs[32 * TK];           // 8 KB
    __shared__ float Wt[32 * (TK + 1)];     // transposed W tile, padded (8.3 KB)

    int row0 = blockIdx.x * 32;
    int col  = threadIdx.x & 31;
    int rgrp = threadIdx.x >> 5;            // 0..7 -> rows rgrp*4 .. rgrp*4+3

    float acc0 = 0.f, acc1 = 0.f, acc2 = 0.f, acc3 = 0.f;

    for (int k0 = 0; k0 < IN_FEAT; k0 += TK) {
        // load X tile: 32 rows x 64 k (512 float4, 2 per thread)
        #pragma unroll
        for (int i = 0; i < 2; i++) {
            int idx = threadIdx.x + i * 256;        // 0..511
            int r  = idx >> 4;                      // 0..31
            int c4 = idx & 15;                      // 0..15
            float4 v = *(const float4*)(x + (size_t)(row0 + r) * IN_FEAT + k0 + c4 * 4);
            *(float4*)(Xs + r * TK + c4 * 4) = v;
        }
        // load W tile transposed: Wt[c][kk] = W[(k0+kk)*32 + c]
        #pragma unroll
        for (int i = 0; i < 8; i++) {
            int idx = threadIdx.x + i * 256;        // 0..2047
            int kk = idx >> 5;                      // 0..63
            int c  = idx & 31;
            Wt[c * (TK + 1) + kk] = W[(size_t)(k0 + kk) * HID + c];
        }
        __syncthreads();

        #pragma unroll
        for (int kk = 0; kk < TK; kk += 4) {
            float w0 = Wt[col * (TK + 1) + kk + 0];
            float w1 = Wt[col * (TK + 1) + kk + 1];
            float w2 = Wt[col * (TK + 1) + kk + 2];
            float w3 = Wt[col * (TK + 1) + kk + 3];
            float4 x0v = *(const float4*)(Xs + (rgrp * 4 + 0) * TK + kk);
            float4 x1v = *(const float4*)(Xs + (rgrp * 4 + 1) * TK + kk);
            float4 x2v = *(const float4*)(Xs + (rgrp * 4 + 2) * TK + kk);
            float4 x3v = *(const float4*)(Xs + (rgrp * 4 + 3) * TK + kk);
            acc0 += x0v.x * w0 + x0v.y * w1 + x0v.z * w2 + x0v.w * w3;
            acc1 += x1v.x * w0 + x1v.y * w1 + x1v.z * w2 + x1v.w * w3;
            acc2 += x2v.x * w0 + x2v.y * w1 + x2v.z * w2 + x2v.w * w3;
            acc3 += x3v.x * w0 + x3v.y * w1 + x3v.z * w2 + x3v.w * w3;
        }
        __syncthreads();
    }
    int rb = row0 + rgrp * 4;
    out[(size_t)(rb + 0) * HID + col] = acc0;
    out[(size_t)(rb + 1) * HID + col] = acc1;
    out[(size_t)(rb + 2) * HID + col] = acc2;
    out[(size_t)(rb + 3) * HID + col] = acc3;
}

// ---------------- small GEMM with ReLU on input: [N,32] @ [32,32] ----------------
// 256 threads = 8 warps; warp per row, lane per col. W transposed in smem.
__global__ __launch_bounds__(256) void gemm_small_relu_kernel(
    const float* __restrict__ xin, const float* __restrict__ W,
    float* __restrict__ out)
{
    __shared__ float Ws[32 * 33];  // Ws[col*33 + k] = W[k*32 + col]
    for (int i = threadIdx.x; i < 32 * 32; i += 256)
        Ws[(i & 31) * 33 + (i >> 5)] = W[i];
    __syncthreads();

    int row = blockIdx.x * 8 + (threadIdx.x >> 5);
    int col = threadIdx.x & 31;
    const float* xr = xin + (size_t)row * HID;
    float acc = 0.f;
    #pragma unroll
    for (int k = 0; k < HID; k++) {
        float xv = fmaxf(xr[k], 0.0f);   // ReLU from previous layer, fused
        acc += xv * Ws[col * 33 + k];
    }
    out[(size_t)row * HID + col] = acc;
}

// ---------------- init agg with self-loop term + bias ----------------
__global__ void init_agg_kernel(const float* __restrict__ h,
                                const float* __restrict__ b,
                                float* __restrict__ agg)
{
    int i = blockIdx.x * blockDim.x + threadIdx.x;   // < N_NODES*HID
    int node = i >> 5;
    int col  = i & 31;
    float dv = g_dinv[node];
    agg[i] = h[i] * dv * dv + b[col];
}

// ---------------- edge scatter: agg[dst] += norm * h[src] ----------------
// 8 threads per edge; each handles one float4 (32 floats/row total).
__global__ void scatter_kernel(const int* __restrict__ src,
                               const int* __restrict__ dst,
                               const float* __restrict__ h,
                               float* __restrict__ agg)
{
    long long t = (long long)blockIdx.x * blockDim.x + threadIdx.x;
    if (t >= (long long)N_EDGES * 8) return;
    int e = (int)(t >> 3);
    int c = (int)(t & 7) * 4;
    int s = src[e];
    int d = dst[e];
    float norm = g_dinv[s] * g_dinv[d];
    float4 v = *(const float4*)(h + (size_t)s * HID + c);
    float4 m = make_float4(v.x * norm, v.y * norm, v.z * norm, v.w * norm);
    atomicAdd((float4*)(agg + (size_t)d * HID + c), m);   // vector RED, sm_90+
}

// ---------------- final MLP: relu(x3) @ lin1 (+b, relu) @ lin2 (+b) ----------------
// warp per node.
__global__ __launch_bounds__(128) void mlp_kernel(
    const float* __restrict__ xin,
    const float* __restrict__ l1W, const float* __restrict__ l1b,
    const float* __restrict__ l2W, const float* __restrict__ l2b,
    float* __restrict__ out)
{
    int node = blockIdx.x * 4 + (threadIdx.x >> 5);
    int lane = threadIdx.x & 31;
    if (node >= N_NODES) return;

    float v = fmaxf(xin[(size_t)node * HID + lane], 0.0f);

    float a1 = 0.f;
    #pragma unroll
    for (int k = 0; k < 32; k++) {
        float xv = __shfl_sync(0xffffffffu, v, k);
        if (lane < 16) a1 += xv * l1W[k * 16 + lane];
    }
    float h1 = (lane < 16) ? fmaxf(a1 + l1b[lane], 0.0f) : 0.0f;

    float a2 = 0.f;
    #pragma unroll
    for (int j = 0; j < 16; j++) {
        float hv = __shfl_sync(0xffffffffu, h1, j);
        if (lane < 10) a2 += hv * l2W[j * 10 + lane];
    }
    if (lane < 10) out[(size_t)node * 10 + lane] = a2 + l2b[lane];
}

// ---------------- host ----------------
extern "C" void kernel_launch(void* const* d_in, const int* in_sizes, int n_in,
                              void* d_out, int out_size)
{
    const float* x0  = (const float*)d_in[0];
    const int*   ei  = (const int*)d_in[1];   // edge_index, int32 (JAX x64 disabled)
    // d_in[2] = batch (unused)
    const float* W1  = (const float*)d_in[3];
    const float* b1  = (const float*)d_in[4];
    const float* W2  = (const float*)d_in[5];
    const float* b2  = (const float*)d_in[6];
    const float* W3  = (const float*)d_in[7];
    const float* b3  = (const float*)d_in[8];
    const float* l1W = (const float*)d_in[9];
    const float* l1b = (const float*)d_in[10];
    const float* l2W = (const float*)d_in[11];
    const float* l2b = (const float*)d_in[12];
    float* out = (float*)d_out;

    const int* src = ei;
    const int* dst = ei + N_EDGES;

    float *hbuf = nullptr, *abuf = nullptr;
    cudaGetSymbolAddress((void**)&hbuf, g_h);
    cudaGetSymbolAddress((void**)&abuf, g_agg);

    const int nodeBlocks  = (N_NODES + 255) / 256;          // 391
    const int edgeBlocks  = N_EDGES / 256;                  // 12500
    const int featBlocks  = (N_NODES * HID) / 256;          // 12500
    const int scatBlocks  = (int)(((long long)N_EDGES * 8) / 256);  // 100000

    // degree + normalization
    zero_deg_kernel<<<nodeBlocks, 256>>>();
    deg_kernel<<<edgeBlocks, 256>>>(dst);
    dinv_kernel<<<nodeBlocks, 256>>>();

    // ---- layer 1 ----
    gemm1_kernel<<<N_NODES / 32, 256>>>(x0, W1, hbuf);
    init_agg_kernel<<<featBlocks, 256>>>(hbuf, b1, abuf);
    scatter_kernel<<<scatBlocks, 256>>>(src, dst, hbuf, abuf);

    // ---- layer 2 ---- (relu of agg fused into GEMM input read)
    gemm_small_relu_kernel<<<N_NODES / 8, 256>>>(abuf, W2, hbuf);
    init_agg_kernel<<<featBlocks, 256>>>(hbuf, b2, abuf);
    scatter_kernel<<<scatBlocks, 256>>>(src, dst, hbuf, abuf);

    // ---- layer 3 ----
    gemm_small_relu_kernel<<<N_NODES / 8, 256>>>(abuf, W3, hbuf);
    init_agg_kernel<<<featBlocks, 256>>>(hbuf, b3, abuf);
    scatter_kernel<<<scatBlocks, 256>>>(src, dst, hbuf, abuf);

    // ---- MLP head ----
    mlp_kernel<<<N_NODES / 4, 128>>>(abuf, l1W, l1b, l2W, l2b, out);
}

// round 7
// speedup vs baseline: 1.2121x; 1.2121x over previous
#include <cuda_runtime.h>
#include <cuda_bf16.h>

#define N_NODES 100000
#define N_EDGES 3200000
#define IN_FEAT 512
#define HID 32
#define SCAN_BLK 512
#define SCAN_NBLK ((N_NODES + SCAN_BLK - 1) / SCAN_BLK)   // 196

// ---------------- device scratch (static, no allocation) ----------------
__device__ int   g_degi[N_NODES];
__device__ float g_dinv[N_NODES];
__device__ int   g_rowstart[N_NODES + 1];
__device__ int   g_cursor[N_NODES];
__device__ int   g_blocksum[SCAN_NBLK];
__device__ int   g_blockoff[SCAN_NBLK];
__device__ int   g_csrc[N_EDGES];
__device__ float g_h[(size_t)N_NODES * HID];    // hh = (x W) * dinv[row]
__device__ float g_agg[(size_t)N_NODES * HID];  // aggregated layer output

// ---------------- f32x2 helpers ----------------
__device__ __forceinline__ unsigned long long fma2(unsigned long long a,
                                                   unsigned long long b,
                                                   unsigned long long c) {
    unsigned long long d;
    asm("fma.rn.f32x2 %0, %1, %2, %3;" : "=l"(d) : "l"(a), "l"(b), "l"(c));
    return d;
}
__device__ __forceinline__ unsigned long long pack2(float lo, float hi) {
    unsigned long long d;
    asm("mov.b64 %0, {%1, %2};" : "=l"(d) : "f"(lo), "f"(hi));
    return d;
}
__device__ __forceinline__ void unpack2(unsigned long long v, float& lo, float& hi) {
    asm("mov.b64 {%0, %1}, %2;" : "=f"(lo), "=f"(hi) : "l"(v));
}

// ---------------- degree / norm / CSR build ----------------
__global__ void zero_degi_kernel() {
    int i = blockIdx.x * blockDim.x + threadIdx.x;
    if (i < N_NODES) g_degi[i] = 0;
}

__global__ void degi_kernel(const int* __restrict__ dst) {
    int e = blockIdx.x * blockDim.x + threadIdx.x;
    if (e < N_EDGES) atomicAdd(&g_degi[dst[e]], 1);
}

__global__ void dinv_kernel() {
    int i = blockIdx.x * blockDim.x + threadIdx.x;
    if (i < N_NODES) g_dinv[i] = rsqrtf((float)g_degi[i] + 1.0f);
}

__global__ void scan_block_kernel() {
    __shared__ int sh[SCAN_BLK];
    int i = blockIdx.x * SCAN_BLK + threadIdx.x;
    int v = (i < N_NODES) ? g_degi[i] : 0;
    sh[threadIdx.x] = v;
    __syncthreads();
    #pragma unroll
    for (int off = 1; off < SCAN_BLK; off <<= 1) {
        int t = (threadIdx.x >= off) ? sh[threadIdx.x - off] : 0;
        __syncthreads();
        sh[threadIdx.x] += t;
        __syncthreads();
    }
    if (i < N_NODES) g_rowstart[i] = sh[threadIdx.x] - v;   // exclusive, block-local
    if (threadIdx.x == SCAN_BLK - 1) g_blocksum[blockIdx.x] = sh[SCAN_BLK - 1];
}

__global__ void scan_tops_kernel() {
    if (threadIdx.x == 0) {
        int run = 0;
        for (int b = 0; b < SCAN_NBLK; b++) {
            g_blockoff[b] = run;
            run += g_blocksum[b];
        }
        g_rowstart[N_NODES] = run;   // == N_EDGES
    }
}

__global__ void scan_add_kernel() {
    int i = blockIdx.x * blockDim.x + threadIdx.x;
    if (i < N_NODES) {
        int v = g_rowstart[i] + g_blockoff[i >> 9];   // 512 = 1<<9
        g_rowstart[i] = v;
        g_cursor[i] = v;
    }
}

__global__ void fill_kernel(const int* __restrict__ src, const int* __restrict__ dst) {
    int e = blockIdx.x * blockDim.x + threadIdx.x;
    if (e < N_EDGES) {
        int d = dst[e];
        int pos = atomicAdd(&g_cursor[d], 1);
        g_csrc[pos] = src[e];
    }
}

// ---------------- GEMM1: [N,512] @ [512,32], f32x2 packed ----------------
// 128 threads/block, tile = 256 rows x 32 cols. Thread: 8 rows (4 f32x2 pairs)
// x 8 cols = 64 outputs. W duplicated to float2 in shared -> LDS.64 broadcast,
// each W load feeds 4 FMA2. Epilogue scales by dinv[row] (hh = h * dinv).
// NOTE: Xs row pitch MUST stay 16 floats (64 B) so float4 slices are aligned;
// the resulting 8-way bank conflict on X reads costs ~64 smem-cycles per
// kk4-block vs 256 FMA-cycles, so it is hidden.
#define G1_ROWS 256
#define G1_TK 16
__global__ __launch_bounds__(128) void gemm1_kernel(
    const float* __restrict__ x, const float* __restrict__ W,
    float* __restrict__ hh)
{
    __shared__ float  Xs[G1_ROWS][G1_TK];       // 16 KB, 64B row pitch (aligned)
    __shared__ float2 Ws2[G1_TK][HID];          // 4 KB

    int tid = threadIdx.x;
    int cid = tid & 3;          // col group: cols cid*8 .. cid*8+7
    int rid = tid >> 2;         // 0..31: rows rid*8 .. rid*8+7
    int rowbase = blockIdx.x * G1_ROWS;

    unsigned long long acc[4][8];
    #pragma unroll
    for (int p = 0; p < 4; p++)
        #pragma unroll
        for (int c = 0; c < 8; c++) acc[p][c] = 0ull;

    for (int k0 = 0; k0 < IN_FEAT; k0 += G1_TK) {
        // load X tile: 256 rows x 16 k = 1024 float4, 8 per thread, coalesced
        #pragma unroll
        for (int i = 0; i < 8; i++) {
            int flat = tid + i * 128;            // 0..1023
            int r  = flat >> 2;
            int c4 = flat & 3;
            int gr = rowbase + r;
            if (gr >= N_NODES) gr = N_NODES - 1;
            float4 v = *(const float4*)(x + (size_t)gr * IN_FEAT + k0 + c4 * 4);
            *(float4*)(&Xs[r][c4 * 4]) = v;
        }
        // load W tile duplicated: Ws2[kk][c] = (w, w)
        #pragma unroll
        for (int i = 0; i < 4; i++) {
            int idx = tid + i * 128;             // 0..511
            int kk = idx >> 5;
            int c  = idx & 31;
            float w = W[(size_t)(k0 + kk) * HID + c];
            Ws2[kk][c] = make_float2(w, w);
        }
        __syncthreads();

        #pragma unroll
        for (int kk4 = 0; kk4 < G1_TK; kk4 += 4) {
            unsigned long long xp[4][4];
            #pragma unroll
            for (int p = 0; p < 4; p++) {
                float4 xa = *(const float4*)(&Xs[rid * 8 + 2 * p + 0][kk4]);
                float4 xb = *(const float4*)(&Xs[rid * 8 + 2 * p + 1][kk4]);
                xp[p][0] = pack2(xa.x, xb.x);
                xp[p][1] = pack2(xa.y, xb.y);
                xp[p][2] = pack2(xa.z, xb.z);
                xp[p][3] = pack2(xa.w, xb.w);
            }
            #pragma unroll
            for (int kkk = 0; kkk < 4; kkk++) {
                #pragma unroll
                for (int c = 0; c < 8; c++) {
                    unsigned long long wp =
                        *(const unsigned long long*)(&Ws2[kk4 + kkk][cid * 8 + c]);
                    #pragma unroll
                    for (int p = 0; p < 4; p++)
                        acc[p][c] = fma2(xp[p][kkk], wp, acc[p][c]);
                }
            }
        }
        __syncthreads();
    }

    // epilogue: unpack, scale by dinv[row], store
    #pragma unroll
    for (int p = 0; p < 4; p++) {
        int r0 = rowbase + rid * 8 + 2 * p;
        int r1 = r0 + 1;
        float lo[8], hi[8];
        #pragma unroll
        for (int c = 0; c < 8; c++) unpack2(acc[p][c], lo[c], hi[c]);
        if (r0 < N_NODES) {
            float d0 = g_dinv[r0];
            float4 v0 = make_float4(lo[0]*d0, lo[1]*d0, lo[2]*d0, lo[3]*d0);
            float4 v1 = make_float4(lo[4]*d0, lo[5]*d0, lo[6]*d0, lo[7]*d0);
            *(float4*)(hh + (size_t)r0 * HID + cid * 8 + 0) = v0;
            *(float4*)(hh + (size_t)r0 * HID + cid * 8 + 4) = v1;
        }
        if (r1 < N_NODES) {
            float d1 = g_dinv[r1];
            float4 v0 = make_float4(hi[0]*d1, hi[1]*d1, hi[2]*d1, hi[3]*d1);
            float4 v1 = make_float4(hi[4]*d1, hi[5]*d1, hi[6]*d1, hi[7]*d1);
            *(float4*)(hh + (size_t)r1 * HID + cid * 8 + 0) = v0;
            *(float4*)(hh + (size_t)r1 * HID + cid * 8 + 4) = v1;
        }
    }
}

// ---------------- small GEMM: hh = (relu(agg) @ W) * dinv[row] ----------------
__global__ __launch_bounds__(256) void gemm_small_kernel(
    const float* __restrict__ agg, const float* __restrict__ W,
    float* __restrict__ hh)
{
    __shared__ float Ws[HID * 33];  // Ws[col*33 + k] = W[k*32 + col]
    for (int i = threadIdx.x; i < HID * HID; i += 256)
        Ws[(i & 31) * 33 + (i >> 5)] = W[i];
    __syncthreads();

    int row = blockIdx.x * 8 + (threadIdx.x >> 5);
    int col = threadIdx.x & 31;
    const float* xr = agg + (size_t)row * HID;
    float acc = 0.f;
    #pragma unroll
    for (int k = 0; k < HID; k++) {
        float xv = fmaxf(xr[k], 0.0f);
        acc += xv * Ws[col * 33 + k];
    }
    hh[(size_t)row * HID + col] = acc * g_dinv[row];
}

// ---------------- CSR gather: agg[d] = dinv[d]*(sum hh[src] + hh[d]) + b ----
// warp per node, lane = feature column. One coalesced 128B load per edge.
__global__ __launch_bounds__(256) void gather_bias_kernel(
    const float* __restrict__ hh, const float* __restrict__ b,
    float* __restrict__ agg)
{
    int node = blockIdx.x * 8 + (threadIdx.x >> 5);
    int lane = threadIdx.x & 31;
    int start = g_rowstart[node];
    int end   = g_rowstart[node + 1];

    float acc0 = 0.f, acc1 = 0.f;
    for (int base = start; base < end; base += 32) {
        int e = base + lane;
        int sidx = (e < end) ? g_csrc[e] : 0;
        int n = end - base;
        if (n >= 32) {
            #pragma unroll
            for (int j = 0; j < 32; j += 2) {
                int s0 = __shfl_sync(0xffffffffu, sidx, j);
                int s1 = __shfl_sync(0xffffffffu, sidx, j + 1);
                acc0 += hh[(size_t)s0 * HID + lane];
                acc1 += hh[(size_t)s1 * HID + lane];
            }
        } else {
            for (int j = 0; j < n; j++) {
                int s = __shfl_sync(0xffffffffu, sidx, j);
                acc0 += hh[(size_t)s * HID + lane];
            }
        }
    }
    float dv = g_dinv[node];
    float self = hh[(size_t)node * HID + lane];
    agg[(size_t)node * HID + lane] = dv * (acc0 + acc1 + self) + b[lane];
}

// ---------------- fused layer-3 gather + MLP head ----------------
__global__ __launch_bounds__(256) void gather_mlp_kernel(
    const float* __restrict__ hh, const float* __restrict__ b3,
    const float* __restrict__ l1W, const float* __restrict__ l1b,
    const float* __restrict__ l2W, const float* __restrict__ l2b,
    float* __restrict__ out)
{
    int node = blockIdx.x * 8 + (threadIdx.x >> 5);
    int lane = threadIdx.x & 31;
    int start = g_rowstart[node];
    int end   = g_rowstart[node + 1];

    float acc0 = 0.f, acc1 = 0.f;
    for (int base = start; base < end; base += 32) {
        int e = base + lane;
        int sidx = (e < end) ? g_csrc[e] : 0;
        int n = end - base;
        if (n >= 32) {
            #pragma unroll
            for (int j = 0; j < 32; j += 2) {
                int s0 = __shfl_sync(0xffffffffu, sidx, j);
                int s1 = __shfl_sync(0xffffffffu, sidx, j + 1);
                acc0 += hh[(size_t)s0 * HID + lane];
                acc1 += hh[(size_t)s1 * HID + lane];
            }
        } else {
            for (int j = 0; j < n; j++) {
                int s = __shfl_sync(0xffffffffu, sidx, j);
                acc0 += hh[(size_t)s * HID + lane];
            }
        }
    }
    float dv = g_dinv[node];
    float self = hh[(size_t)node * HID + lane];
    float v = fmaxf(dv * (acc0 + acc1 + self) + b3[lane], 0.0f);  // x3

    // lin1: [32] -> [16], relu
    float a1 = 0.f;
    #pragma unroll
    for (int k = 0; k < 32; k++) {
        float xv = __shfl_sync(0xffffffffu, v, k);
        if (lane < 16) a1 += xv * l1W[k * 16 + lane];
    }
    float h1 = (lane < 16) ? fmaxf(a1 + l1b[lane], 0.0f) : 0.0f;

    // lin2: [16] -> [10]
    float a2 = 0.f;
    #pragma unroll
    for (int j = 0; j < 16; j++) {
        float hv = __shfl_sync(0xffffffffu, h1, j);
        if (lane < 10) a2 += hv * l2W[j * 10 + lane];
    }
    if (lane < 10) out[(size_t)node * 10 + lane] = a2 + l2b[lane];
}

// ---------------- host ----------------
extern "C" void kernel_launch(void* const* d_in, const int* in_sizes, int n_in,
                              void* d_out, int out_size)
{
    const float* x0  = (const float*)d_in[0];
    const int*   ei  = (const int*)d_in[1];   // edge_index int32
    // d_in[2] = batch (unused)
    const float* W1  = (const float*)d_in[3];
    const float* b1  = (const float*)d_in[4];
    const float* W2  = (const float*)d_in[5];
    const float* b2  = (const float*)d_in[6];
    const float* W3  = (const float*)d_in[7];
    const float* b3  = (const float*)d_in[8];
    const float* l1W = (const float*)d_in[9];
    const float* l1b = (const float*)d_in[10];
    const float* l2W = (const float*)d_in[11];
    const float* l2b = (const float*)d_in[12];
    float* out = (float*)d_out;

    const int* src = ei;
    const int* dst = ei + N_EDGES;

    float *hbuf = nullptr, *abuf = nullptr;
    cudaGetSymbolAddress((void**)&hbuf, g_h);
    cudaGetSymbolAddress((void**)&abuf, g_agg);

    const int nodeBlocks = (N_NODES + 255) / 256;   // 391
    const int edgeBlocks = N_EDGES / 256;           // 12500
    const int warpBlocks = N_NODES / 8;             // 12500
    const int g1Blocks   = (N_NODES + G1_ROWS - 1) / G1_ROWS;  // 391

    // ---- CSR build (once per launch; shared by all 3 layers) ----
    zero_degi_kernel<<<nodeBlocks, 256>>>();
    degi_kernel<<<edgeBlocks, 256>>>(dst);
    dinv_kernel<<<nodeBlocks, 256>>>();
    scan_block_kernel<<<SCAN_NBLK, SCAN_BLK>>>();
    scan_tops_kernel<<<1, 32>>>();
    scan_add_kernel<<<nodeBlocks, 256>>>();
    fill_kernel<<<edgeBlocks, 256>>>(src, dst);

    // ---- layer 1 ----
    gemm1_kernel<<<g1Blocks, 128>>>(x0, W1, hbuf);
    gather_bias_kernel<<<warpBlocks, 256>>>(hbuf, b1, abuf);

    // ---- layer 2 ----
    gemm_small_kernel<<<warpBlocks, 256>>>(abuf, W2, hbuf);
    gather_bias_kernel<<<warpBlocks, 256>>>(hbuf, b2, abuf);

    // ---- layer 3 + MLP head (fused) ----
    gemm_small_kernel<<<warpBlocks, 256>>>(abuf, W3, hbuf);
    gather_mlp_kernel<<<warpBlocks, 256>>>(hbuf, b3, l1W, l1b, l2W, l2b, out);
}

// round 8
// speedup vs baseline: 1.3190x; 1.0881x over previous
#include <cuda_runtime.h>
#include <cuda_bf16.h>

#define N_NODES 100000
#define N_EDGES 3200000
#define IN_FEAT 512
#define HID 32
#define SCAN_BLK 512
#define SCAN_NBLK ((N_NODES + SCAN_BLK - 1) / SCAN_BLK)   // 196

// ---------------- device scratch (static, no allocation) ----------------
__device__ int   g_degi[N_NODES];
__device__ float g_dinv[N_NODES];
__device__ int   g_rowstart[N_NODES + 1];
__device__ int   g_cursor[N_NODES];
__device__ int   g_blocksum[SCAN_NBLK];
__device__ int   g_blockoff[SCAN_NBLK];
__device__ int   g_csrc[N_EDGES];
__device__ float g_h[(size_t)N_NODES * HID];    // ping
__device__ float g_agg[(size_t)N_NODES * HID];  // pong

// ---------------- f32x2 helpers ----------------
__device__ __forceinline__ unsigned long long fma2(unsigned long long a,
                                                   unsigned long long b,
                                                   unsigned long long c) {
    unsigned long long d;
    asm("fma.rn.f32x2 %0, %1, %2, %3;" : "=l"(d) : "l"(a), "l"(b), "l"(c));
    return d;
}
__device__ __forceinline__ unsigned long long pack2(float lo, float hi) {
    unsigned long long d;
    asm("mov.b64 %0, {%1, %2};" : "=l"(d) : "f"(lo), "f"(hi));
    return d;
}
__device__ __forceinline__ void unpack2(unsigned long long v, float& lo, float& hi) {
    asm("mov.b64 {%0, %1}, %2;" : "=f"(lo), "=f"(hi) : "l"(v));
}

// ---------------- degree / CSR build ----------------
__global__ void zero_degi_kernel() {
    int i = blockIdx.x * blockDim.x + threadIdx.x;
    if (i < N_NODES) g_degi[i] = 0;
}

__global__ void degi_kernel(const int* __restrict__ dst) {
    int e = blockIdx.x * blockDim.x + threadIdx.x;
    if (e < N_EDGES) atomicAdd(&g_degi[dst[e]], 1);
}

// block-local exclusive scan of degrees; also computes dinv (fused).
__global__ void scan_block_kernel() {
    __shared__ int sh[SCAN_BLK];
    int i = blockIdx.x * SCAN_BLK + threadIdx.x;
    int v = (i < N_NODES) ? g_degi[i] : 0;
    if (i < N_NODES) g_dinv[i] = rsqrtf((float)v + 1.0f);
    sh[threadIdx.x] = v;
    __syncthreads();
    #pragma unroll
    for (int off = 1; off < SCAN_BLK; off <<= 1) {
        int t = (threadIdx.x >= off) ? sh[threadIdx.x - off] : 0;
        __syncthreads();
        sh[threadIdx.x] += t;
        __syncthreads();
    }
    if (i < N_NODES) g_rowstart[i] = sh[threadIdx.x] - v;   // exclusive, block-local
    if (threadIdx.x == SCAN_BLK - 1) g_blocksum[blockIdx.x] = sh[SCAN_BLK - 1];
}

// parallel scan of the 196 block sums (single 256-thread block).
__global__ void scan_tops_kernel() {
    __shared__ int sh[256];
    int t = threadIdx.x;
    int v = (t < SCAN_NBLK) ? g_blocksum[t] : 0;
    sh[t] = v;
    __syncthreads();
    #pragma unroll
    for (int off = 1; off < 256; off <<= 1) {
        int x = (t >= off) ? sh[t - off] : 0;
        __syncthreads();
        sh[t] += x;
        __syncthreads();
    }
    if (t < SCAN_NBLK) g_blockoff[t] = sh[t] - v;   // exclusive
    if (t == 255) g_rowstart[N_NODES] = sh[255];    // == N_EDGES
}

__global__ void scan_add_kernel() {
    int i = blockIdx.x * blockDim.x + threadIdx.x;
    if (i < N_NODES) {
        int v = g_rowstart[i] + g_blockoff[i >> 9];   // 512 = 1<<9
        g_rowstart[i] = v;
        g_cursor[i] = v;
    }
}

__global__ void fill_kernel(const int* __restrict__ src, const int* __restrict__ dst) {
    int e = blockIdx.x * blockDim.x + threadIdx.x;
    if (e < N_EDGES) {
        int d = dst[e];
        int pos = atomicAdd(&g_cursor[d], 1);
        g_csrc[pos] = src[e];
    }
}

// ---------------- GEMM1: [N,512] @ [512,32], f32x2 packed ----------------
// 128 threads/block, tile = 256 rows x 32 cols. Thread: 8 rows (4 f32x2 pairs)
// x 8 cols = 64 outputs. W duplicated to float2 in shared -> LDS.64 broadcast,
// each W load feeds 4 FMA2. Epilogue scales by dinv[row] (hh = h * dinv).
// Xs row pitch = 16 floats (64 B) so float4 slices stay 16B-aligned.
#define G1_ROWS 256
#define G1_TK 16
__global__ __launch_bounds__(128) void gemm1_kernel(
    const float* __restrict__ x, const float* __restrict__ W,
    float* __restrict__ hh)
{
    __shared__ float  Xs[G1_ROWS][G1_TK];       // 16 KB
    __shared__ float2 Ws2[G1_TK][HID];          // 4 KB

    int tid = threadIdx.x;
    int cid = tid & 3;          // col group: cols cid*8 .. cid*8+7
    int rid = tid >> 2;         // 0..31: rows rid*8 .. rid*8+7
    int rowbase = blockIdx.x * G1_ROWS;

    unsigned long long acc[4][8];
    #pragma unroll
    for (int p = 0; p < 4; p++)
        #pragma unroll
        for (int c = 0; c < 8; c++) acc[p][c] = 0ull;

    for (int k0 = 0; k0 < IN_FEAT; k0 += G1_TK) {
        #pragma unroll
        for (int i = 0; i < 8; i++) {
            int flat = tid + i * 128;            // 0..1023
            int r  = flat >> 2;
            int c4 = flat & 3;
            int gr = rowbase + r;
            if (gr >= N_NODES) gr = N_NODES - 1;
            float4 v = *(const float4*)(x + (size_t)gr * IN_FEAT + k0 + c4 * 4);
            *(float4*)(&Xs[r][c4 * 4]) = v;
        }
        #pragma unroll
        for (int i = 0; i < 4; i++) {
            int idx = tid + i * 128;             // 0..511
            int kk = idx >> 5;
            int c  = idx & 31;
            float w = W[(size_t)(k0 + kk) * HID + c];
            Ws2[kk][c] = make_float2(w, w);
        }
        __syncthreads();

        #pragma unroll
        for (int kk4 = 0; kk4 < G1_TK; kk4 += 4) {
            unsigned long long xp[4][4];
            #pragma unroll
            for (int p = 0; p < 4; p++) {
                float4 xa = *(const float4*)(&Xs[rid * 8 + 2 * p + 0][kk4]);
                float4 xb = *(const float4*)(&Xs[rid * 8 + 2 * p + 1][kk4]);
                xp[p][0] = pack2(xa.x, xb.x);
                xp[p][1] = pack2(xa.y, xb.y);
                xp[p][2] = pack2(xa.z, xb.z);
                xp[p][3] = pack2(xa.w, xb.w);
            }
            #pragma unroll
            for (int kkk = 0; kkk < 4; kkk++) {
                #pragma unroll
                for (int c = 0; c < 8; c++) {
                    unsigned long long wp =
                        *(const unsigned long long*)(&Ws2[kk4 + kkk][cid * 8 + c]);
                    #pragma unroll
                    for (int p = 0; p < 4; p++)
                        acc[p][c] = fma2(xp[p][kkk], wp, acc[p][c]);
                }
            }
        }
        __syncthreads();
    }

    #pragma unroll
    for (int p = 0; p < 4; p++) {
        int r0 = rowbase + rid * 8 + 2 * p;
        int r1 = r0 + 1;
        float lo[8], hi[8];
        #pragma unroll
        for (int c = 0; c < 8; c++) unpack2(acc[p][c], lo[c], hi[c]);
        if (r0 < N_NODES) {
            float d0 = g_dinv[r0];
            float4 v0 = make_float4(lo[0]*d0, lo[1]*d0, lo[2]*d0, lo[3]*d0);
            float4 v1 = make_float4(lo[4]*d0, lo[5]*d0, lo[6]*d0, lo[7]*d0);
            *(float4*)(hh + (size_t)r0 * HID + cid * 8 + 0) = v0;
            *(float4*)(hh + (size_t)r0 * HID + cid * 8 + 4) = v1;
        }
        if (r1 < N_NODES) {
            float d1 = g_dinv[r1];
            float4 v0 = make_float4(hi[0]*d1, hi[1]*d1, hi[2]*d1, hi[3]*d1);
            float4 v1 = make_float4(hi[4]*d1, hi[5]*d1, hi[6]*d1, hi[7]*d1);
            *(float4*)(hh + (size_t)r1 * HID + cid * 8 + 0) = v0;
            *(float4*)(hh + (size_t)r1 * HID + cid * 8 + 4) = v1;
        }
    }
}

// ---------------- fused gather + next-layer GEMM ----------------
// warp per node, lane = feature column.
// val = dinv[d]*(sum_src hh_in[src] + hh_in[d]) + b[lane]  (= agg, this layer)
// v   = relu(val)
// hh_out[d][col] = (sum_k v_k * W[k][col]) * dinv[d]        (= next layer's hh)
// The 32x32 GEMM runs in-warp: v_k broadcast by shfl, W from smem (row k
// contiguous across lanes -> conflict-free).
__global__ __launch_bounds__(256) void gather_gemm_kernel(
    const float* __restrict__ hh_in, const float* __restrict__ b,
    const float* __restrict__ W, float* __restrict__ hh_out)
{
    __shared__ float Ws[HID * HID];   // Ws[k*32 + col] = W[k][col]
    for (int i = threadIdx.x; i < HID * HID; i += 256) Ws[i] = W[i];
    __syncthreads();

    int node = blockIdx.x * 8 + (threadIdx.x >> 5);
    int lane = threadIdx.x & 31;
    int start = g_rowstart[node];
    int end   = g_rowstart[node + 1];

    float acc0 = 0.f, acc1 = 0.f;
    for (int base = start; base < end; base += 32) {
        int e = base + lane;
        int sidx = (e < end) ? g_csrc[e] : 0;
        int n = end - base;
        if (n >= 32) {
            #pragma unroll
            for (int j = 0; j < 32; j += 2) {
                int s0 = __shfl_sync(0xffffffffu, sidx, j);
                int s1 = __shfl_sync(0xffffffffu, sidx, j + 1);
                acc0 += hh_in[(size_t)s0 * HID + lane];
                acc1 += hh_in[(size_t)s1 * HID + lane];
            }
        } else {
            for (int j = 0; j < n; j++) {
                int s = __shfl_sync(0xffffffffu, sidx, j);
                acc0 += hh_in[(size_t)s * HID + lane];
            }
        }
    }
    float dv = g_dinv[node];
    float self = hh_in[(size_t)node * HID + lane];
    float v = fmaxf(dv * (acc0 + acc1 + self) + b[lane], 0.0f);

    float o = 0.f;
    #pragma unroll
    for (int k = 0; k < HID; k++) {
        float xv = __shfl_sync(0xffffffffu, v, k);
        o += xv * Ws[k * HID + lane];
    }
    hh_out[(size_t)node * HID + lane] = o * dv;
}

// ---------------- fused layer-3 gather + MLP head ----------------
__global__ __launch_bounds__(256) void gather_mlp_kernel(
    const float* __restrict__ hh, const float* __restrict__ b3,
    const float* __restrict__ l1W, const float* __restrict__ l1b,
    const float* __restrict__ l2W, const float* __restrict__ l2b,
    float* __restrict__ out)
{
    int node = blockIdx.x * 8 + (threadIdx.x >> 5);
    int lane = threadIdx.x & 31;
    int start = g_rowstart[node];
    int end   = g_rowstart[node + 1];

    float acc0 = 0.f, acc1 = 0.f;
    for (int base = start; base < end; base += 32) {
        int e = base + lane;
        int sidx = (e < end) ? g_csrc[e] : 0;
        int n = end - base;
        if (n >= 32) {
            #pragma unroll
            for (int j = 0; j < 32; j += 2) {
                int s0 = __shfl_sync(0xffffffffu, sidx, j);
                int s1 = __shfl_sync(0xffffffffu, sidx, j + 1);
                acc0 += hh[(size_t)s0 * HID + lane];
                acc1 += hh[(size_t)s1 * HID + lane];
            }
        } else {
            for (int j = 0; j < n; j++) {
                int s = __shfl_sync(0xffffffffu, sidx, j);
                acc0 += hh[(size_t)s * HID + lane];
            }
        }
    }
    float dv = g_dinv[node];
    float self = hh[(size_t)node * HID + lane];
    float v = fmaxf(dv * (acc0 + acc1 + self) + b3[lane], 0.0f);  // x3

    // lin1: [32] -> [16], relu
    float a1 = 0.f;
    #pragma unroll
    for (int k = 0; k < 32; k++) {
        float xv = __shfl_sync(0xffffffffu, v, k);
        if (lane < 16) a1 += xv * l1W[k * 16 + lane];
    }
    float h1 = (lane < 16) ? fmaxf(a1 + l1b[lane], 0.0f) : 0.0f;

    // lin2: [16] -> [10]
    float a2 = 0.f;
    #pragma unroll
    for (int j = 0; j < 16; j++) {
        float hv = __shfl_sync(0xffffffffu, h1, j);
        if (lane < 10) a2 += hv * l2W[j * 10 + lane];
    }
    if (lane < 10) out[(size_t)node * 10 + lane] = a2 + l2b[lane];
}

// ---------------- host ----------------
extern "C" void kernel_launch(void* const* d_in, const int* in_sizes, int n_in,
                              void* d_out, int out_size)
{
    const float* x0  = (const float*)d_in[0];
    const int*   ei  = (const int*)d_in[1];   // edge_index int32
    // d_in[2] = batch (unused)
    const float* W1  = (const float*)d_in[3];
    const float* b1  = (const float*)d_in[4];
    const float* W2  = (const float*)d_in[5];
    const float* b2  = (const float*)d_in[6];
    const float* W3  = (const float*)d_in[7];
    const float* b3  = (const float*)d_in[8];
    const float* l1W = (const float*)d_in[9];
    const float* l1b = (const float*)d_in[10];
    const float* l2W = (const float*)d_in[11];
    const float* l2b = (const float*)d_in[12];
    float* out = (float*)d_out;

    const int* src = ei;
    const int* dst = ei + N_EDGES;

    float *hbuf = nullptr, *abuf = nullptr;
    cudaGetSymbolAddress((void**)&hbuf, g_h);
    cudaGetSymbolAddress((void**)&abuf, g_agg);

    const int nodeBlocks = (N_NODES + 255) / 256;   // 391
    const int edgeBlocks = N_EDGES / 256;           // 12500
    const int warpBlocks = N_NODES / 8;             // 12500
    const int g1Blocks   = (N_NODES + G1_ROWS - 1) / G1_ROWS;  // 391

    // ---- CSR build (shared by all 3 layers) ----
    zero_degi_kernel<<<nodeBlocks, 256>>>();
    degi_kernel<<<edgeBlocks, 256>>>(dst);
    scan_block_kernel<<<SCAN_NBLK, SCAN_BLK>>>();   // also computes dinv
    scan_tops_kernel<<<1, 256>>>();                 // parallel top-level scan
    scan_add_kernel<<<nodeBlocks, 256>>>();
    fill_kernel<<<edgeBlocks, 256>>>(src, dst);

    // ---- layer 1 GEMM ----
    gemm1_kernel<<<g1Blocks, 128>>>(x0, W1, hbuf);                  // hh1

    // ---- gather1 + gemm2 fused ----
    gather_gemm_kernel<<<warpBlocks, 256>>>(hbuf, b1, W2, abuf);    // hh2

    // ---- gather2 + gemm3 fused ----
    gather_gemm_kernel<<<warpBlocks, 256>>>(abuf, b2, W3, hbuf);    // hh3

    // ---- gather3 + MLP head fused ----
    gather_mlp_kernel<<<warpBlocks, 256>>>(hbuf, b3, l1W, l1b, l2W, l2b, out);
}